// round 2
// baseline (speedup 1.0000x reference)
#include <cuda_runtime.h>

#define BATCH 32
#define CH    512
#define HW    4096
#define BN_EPS 1e-5f

// Scratch (device globals — no allocation allowed in kernel_launch)
__device__ float g_pooled[BATCH * CH];   // mean over H,W of x, per (b,c)
__device__ float g_k[CH];                // k[o] = dot(m, W[o,:]) + conv_b[o]

// ---------------------------------------------------------------------------
// Kernel 1: per-(b,c) spatial mean of x. One block per contiguous 4096-float
// plane; 128 threads x 8 float4 loads each (MLP=8, coalesced).
// ---------------------------------------------------------------------------
__global__ void pool_kernel(const float* __restrict__ x) {
    const int idx = blockIdx.x;                      // b*CH + c
    const float4* p = reinterpret_cast<const float4*>(x) + (size_t)idx * (HW / 4);
    const int t = threadIdx.x;

    float s = 0.0f;
#pragma unroll
    for (int j = 0; j < 8; ++j) {
        float4 v = p[t + 128 * j];
        s += (v.x + v.y) + (v.z + v.w);
    }
#pragma unroll
    for (int off = 16; off; off >>= 1)
        s += __shfl_xor_sync(0xffffffffu, s, off);

    __shared__ float sh[4];
    if ((t & 31) == 0) sh[t >> 5] = s;
    __syncthreads();
    if (t == 0) {
        float tot = (sh[0] + sh[1]) + (sh[2] + sh[3]);
        g_pooled[idx] = tot * (1.0f / HW);
    }
}

// ---------------------------------------------------------------------------
// Kernel 2: compute m[c] = sum_{jy,jx} a[jy]*a[jx]*pos[c,jy,jx] (rank-1 mean
// of the half-pixel bilinear upsample), then k[o] = dot(m, W[o,:]) + bias[o].
// Grid 64 x 256 threads: 8 warps/block -> 512 outputs total, warp-per-output
// coalesced float4 reads of W rows. No atomics -> deterministic.
// ---------------------------------------------------------------------------
__global__ void posk_kernel(const float* __restrict__ pos,
                            const float* __restrict__ w,
                            const float* __restrict__ bias) {
    __shared__ float a[7];
    __shared__ __align__(16) float m[CH];
    const int t = threadIdx.x;

    // 1D mean weights a[j]: jax triangle resize with renorm == clamped lerp.
    if (t < 7) {
        float acc = 0.0f;
        for (int i = 0; i < 64; ++i) {
            float s = (i + 0.5f) * (7.0f / 64.0f) - 0.5f;
            s = fminf(fmaxf(s, 0.0f), 6.0f);
            int i0 = (int)floorf(s);
            if (i0 > 5) i0 = 5;          // keep i0+1 in bounds (s==6 -> f==1)
            float f = s - (float)i0;
            if (i0 == t)     acc += 1.0f - f;
            if (i0 + 1 == t) acc += f;
        }
        a[t] = acc * (1.0f / 64.0f);
    }
    __syncthreads();

    // m[c]: 49-tap separable weighted sum of pos_embed.
    for (int c = t; c < CH; c += blockDim.x) {
        const float* pc = pos + c * 49;
        float acc = 0.0f;
#pragma unroll
        for (int jy = 0; jy < 7; ++jy) {
            float row = 0.0f;
#pragma unroll
            for (int jx = 0; jx < 7; ++jx)
                row += a[jx] * pc[jy * 7 + jx];
            acc += a[jy] * row;
        }
        m[c] = acc;
    }
    __syncthreads();

    // k[o] = dot(m, W[o,:]) + bias[o], warp per output channel o.
    const int warp = t >> 5, lane = t & 31;
    const int o = blockIdx.x * 8 + warp;
    const float4* wr = reinterpret_cast<const float4*>(w + o * CH);
    const float4* ms = reinterpret_cast<const float4*>(m);
    float s = 0.0f;
#pragma unroll
    for (int j = 0; j < 4; ++j) {
        float4 wv = wr[lane + 32 * j];
        float4 mv = ms[lane + 32 * j];
        s += wv.x * mv.x + wv.y * mv.y + wv.z * mv.z + wv.w * mv.w;
    }
#pragma unroll
    for (int off = 16; off; off >>= 1)
        s += __shfl_xor_sync(0xffffffffu, s, off);
    if (lane == 0) g_k[o] = s + bias[o];
}

// ---------------------------------------------------------------------------
// Kernel 3: y[b,o] = dot(g_pooled[b,:], W[o,:]) + k[o], then eval-mode BN +
// ReLU. One block per output channel o: W row staged in SMEM (W read exactly
// once from L2 across the grid), warp-per-batch coalesced dots.
// ---------------------------------------------------------------------------
__global__ void gemm_bn_kernel(const float* __restrict__ w,
                               const float* __restrict__ gamma,
                               const float* __restrict__ beta,
                               const float* __restrict__ mean,
                               const float* __restrict__ var,
                               float* __restrict__ out) {
    const int o = blockIdx.x;
    const int t = threadIdx.x;
    __shared__ __align__(16) float wsh[CH];

    const float4* wr = reinterpret_cast<const float4*>(w + o * CH);
    float4* ws4 = reinterpret_cast<float4*>(wsh);
    if (t < 128) ws4[t] = wr[t];
    __syncthreads();

    const float ko  = g_k[o];
    const float g   = gamma[o];
    const float bt  = beta[o];
    const float mn  = mean[o];
    const float inv = rsqrtf(var[o] + BN_EPS);

    const int warp = t >> 5, lane = t & 31;
    for (int b = warp; b < BATCH; b += 8) {
        const float4* pr = reinterpret_cast<const float4*>(g_pooled + b * CH);
        float s = 0.0f;
#pragma unroll
        for (int j = 0; j < 4; ++j) {
            float4 pv = pr[lane + 32 * j];
            float4 wv = ws4[lane + 32 * j];
            s += pv.x * wv.x + pv.y * wv.y + pv.z * wv.z + pv.w * wv.w;
        }
#pragma unroll
        for (int off = 16; off; off >>= 1)
            s += __shfl_xor_sync(0xffffffffu, s, off);
        if (lane == 0) {
            float y = s + ko;
            y = g * (y - mn) * inv + bt;
            out[b * CH + o] = fmaxf(y, 0.0f);
        }
    }
}

// ---------------------------------------------------------------------------
// Inputs (metadata order): x, pos_embed, conv_w, conv_b, bn_gamma, bn_beta,
// bn_mean, bn_var. Output: (32, 512, 1, 1) fp32.
// ---------------------------------------------------------------------------
extern "C" void kernel_launch(void* const* d_in, const int* in_sizes, int n_in,
                              void* d_out, int out_size) {
    const float* x     = (const float*)d_in[0];
    const float* pos   = (const float*)d_in[1];
    const float* w     = (const float*)d_in[2];
    const float* bias  = (const float*)d_in[3];
    const float* gamma = (const float*)d_in[4];
    const float* beta  = (const float*)d_in[5];
    const float* mean  = (const float*)d_in[6];
    const float* var   = (const float*)d_in[7];
    float* out = (float*)d_out;

    pool_kernel<<<BATCH * CH, 128>>>(x);
    posk_kernel<<<64, 256>>>(pos, w, bias);
    gemm_bn_kernel<<<CH, 256>>>(w, gamma, beta, mean, var, out);
}

// round 8
// speedup vs baseline: 1.1908x; 1.1908x over previous
#include <cuda_runtime.h>

#define BATCH 32
#define CH    512
#define HW    4096
#define BN_EPS 1e-5f

// Scratch (device global — no allocation allowed in kernel_launch)
__device__ float g_pooled[BATCH * CH];   // mean_{H,W}(x)[b,c] + m[c]

struct A7 { float a[7]; };               // 1-D bilinear-mean weights (host-computed)

// ---------------------------------------------------------------------------
// Kernel 1: per-(b,c) spatial mean of x, with the rank-1 pos-embed mean m[c]
// folded in (taps pre-scaled by HW, whole sum scaled by 1/HW at the end).
// One block per contiguous 4096-float plane; 128 threads x 8 float4 loads
// (front-batched, MLP=8, coalesced). Triggers PDL so the GEMM kernel can
// stage its weights under this kernel's tail.
// ---------------------------------------------------------------------------
__global__ void pool_kernel(const float* __restrict__ x,
                            const float* __restrict__ pos,
                            A7 aw) {
    const int idx = blockIdx.x;                      // b*CH + c
    const int c   = idx & (CH - 1);
    const float4* p = reinterpret_cast<const float4*>(x) + (size_t)idx * (HW / 4);
    const int t = threadIdx.x;

    // Issue all global loads first (front-batched).
    float4 v[8];
#pragma unroll
    for (int j = 0; j < 8; ++j)
        v[j] = p[t + 128 * j];

    // Allow the dependent GEMM kernel to begin launching/staging.
    if (t == 0) cudaTriggerProgrammaticLaunchCompletion();

    // 49-tap pos-embed contribution: thread t<49 handles tap (jy,jx).
    // Scaled by HW so it rides through the final 1/HW normalization.
    float s = 0.0f;
    if (t < 49) {
        const int jy = t / 7, jx = t - 7 * jy;
        s = aw.a[jy] * aw.a[jx] * (float)HW * __ldg(pos + c * 49 + t);
    }

#pragma unroll
    for (int j = 0; j < 8; ++j)
        s += (v[j].x + v[j].y) + (v[j].z + v[j].w);

#pragma unroll
    for (int off = 16; off; off >>= 1)
        s += __shfl_xor_sync(0xffffffffu, s, off);

    __shared__ float sh[4];
    if ((t & 31) == 0) sh[t >> 5] = s;
    __syncthreads();
    if (t == 0)
        g_pooled[idx] = ((sh[0] + sh[1]) + (sh[2] + sh[3])) * (1.0f / HW);
}

// ---------------------------------------------------------------------------
// Kernel 2 (PDL secondary): y[b,o] = dot(g_pooled[b,:], W[o,:]) + bias[o],
// then eval-mode BN + ReLU. One block per output channel o. W row + BN
// scalars are staged BEFORE cudaGridDependencySynchronize(), overlapping the
// primary kernel's tail; then warp-per-batch coalesced dots over g_pooled.
// cudaGridDependencySynchronize() is a no-op when launched without PDL.
// ---------------------------------------------------------------------------
__global__ void gemm_bn_kernel(const float* __restrict__ w,
                               const float* __restrict__ bias,
                               const float* __restrict__ gamma,
                               const float* __restrict__ beta,
                               const float* __restrict__ mean,
                               const float* __restrict__ var,
                               float* __restrict__ out) {
    const int o = blockIdx.x;
    const int t = threadIdx.x;
    __shared__ __align__(16) float4 ws4[CH / 4];

    // Prologue: independent of the primary kernel's output.
    const float4* wr = reinterpret_cast<const float4*>(w + o * CH);
    if (t < 128) ws4[t] = wr[t];

    const float bo  = bias[o];
    const float g   = gamma[o];
    const float bt  = beta[o];
    const float mn  = mean[o];
    const float inv = rsqrtf(var[o] + BN_EPS);
    __syncthreads();

    // Wait for pool_kernel's writes to be visible.
    cudaGridDependencySynchronize();

    const int warp = t >> 5, lane = t & 31;
    for (int b = warp; b < BATCH; b += 8) {
        const float4* pr = reinterpret_cast<const float4*>(g_pooled + b * CH);
        float s = 0.0f;
#pragma unroll
        for (int j = 0; j < 4; ++j) {
            float4 pv = pr[lane + 32 * j];
            float4 wv = ws4[lane + 32 * j];
            s += pv.x * wv.x + pv.y * wv.y + pv.z * wv.z + pv.w * wv.w;
        }
#pragma unroll
        for (int off = 16; off; off >>= 1)
            s += __shfl_xor_sync(0xffffffffu, s, off);
        if (lane == 0) {
            float y = s + bo;
            y = g * (y - mn) * inv + bt;
            out[b * CH + o] = fmaxf(y, 0.0f);
        }
    }
}

// ---------------------------------------------------------------------------
// Inputs (metadata order): x, pos_embed, conv_w, conv_b, bn_gamma, bn_beta,
// bn_mean, bn_var. Output: (32, 512, 1, 1) fp32.
// ---------------------------------------------------------------------------
extern "C" void kernel_launch(void* const* d_in, const int* in_sizes, int n_in,
                              void* d_out, int out_size) {
    const float* x     = (const float*)d_in[0];
    const float* pos   = (const float*)d_in[1];
    const float* w     = (const float*)d_in[2];
    const float* bias  = (const float*)d_in[3];
    const float* gamma = (const float*)d_in[4];
    const float* beta  = (const float*)d_in[5];
    const float* mean  = (const float*)d_in[6];
    const float* var   = (const float*)d_in[7];
    float* out = (float*)d_out;

    // Host-side: 1-D mean weights of the half-pixel bilinear 7->64 upsample
    // (jax triangle resize with edge renormalization == clamped lerp).
    A7 aw;
    {
        double acc[7] = {0, 0, 0, 0, 0, 0, 0};
        for (int i = 0; i < 64; ++i) {
            double s = (i + 0.5) * (7.0 / 64.0) - 0.5;
            s = s < 0.0 ? 0.0 : (s > 6.0 ? 6.0 : s);
            int i0 = (int)s;
            if (i0 > 5) i0 = 5;
            double f = s - (double)i0;
            acc[i0]     += 1.0 - f;
            acc[i0 + 1] += f;
        }
        for (int j = 0; j < 7; ++j) aw.a[j] = (float)(acc[j] / 64.0);
    }

    pool_kernel<<<BATCH * CH, 128>>>(x, pos, aw);

    // Secondary with programmatic (PDL) dependency on pool_kernel.
    cudaLaunchAttribute attr[1];
    attr[0].id = cudaLaunchAttributeProgrammaticStreamSerialization;
    attr[0].val.programmaticStreamSerializationAllowed = 1;
    cudaLaunchConfig_t cfg = {};
    cfg.gridDim  = dim3(CH);
    cfg.blockDim = dim3(256);
    cfg.dynamicSmemBytes = 0;
    cfg.stream = 0;
    cfg.attrs = attr;
    cfg.numAttrs = 1;
    cudaError_t e = cudaLaunchKernelEx(&cfg, gemm_bn_kernel,
                                       w, bias, gamma, beta, mean, var, out);
    if (e != cudaSuccess) {
        // Fallback: plain stream-ordered launch (correct without PDL overlap).
        (void)cudaGetLastError();  // clear sticky error
        gemm_bn_kernel<<<CH, 256>>>(w, bias, gamma, beta, mean, var, out);
    }
}